// round 2
// baseline (speedup 1.0000x reference)
#include <cuda_runtime.h>
#include <cuda_bf16.h>
#include <math.h>

#define Bb 8
#define Nn 256
#define DEe 768
#define DH 192
#define Ll 2
#define DCc 192
#define G3 576
#define HCW 576

__device__ float g_Hcat[Bb * Nn * HCW];
__device__ float g_GI[Bb * Nn * G3];
__device__ float g_GH[Bb * Nn * G3];
__device__ float g_V0[Bb * Nn * DH];
__device__ float g_V1[Bb * Nn * DH];
__device__ float g_h1[Bb * Nn * DH];
__device__ float g_h2[Bb * Nn * DH];
__device__ float g_WT[2 * DH * G3 + 2 * DH * DH];

__device__ __forceinline__ float warpRedMax(float v) {
#pragma unroll
    for (int o = 16; o > 0; o >>= 1) v = fmaxf(v, __shfl_xor_sync(0xffffffffu, v, o));
    return v;
}
__device__ __forceinline__ float warpRedSum(float v) {
#pragma unroll
    for (int o = 16; o > 0; o >>= 1) v += __shfl_xor_sync(0xffffffffu, v, o);
    return v;
}

// C = act(A @ B + bias). A:(M,K) ld=lda, col offset aoff.
// TRANSB: B is (Nc,K) row-major; else (K,Nc). C: ld=ldc, col offset coff.
template <int TRANSB, int RELU>
__global__ __launch_bounds__(256) void gemm_kernel(
    const float* __restrict__ A, const float* __restrict__ Bm,
    const float* __restrict__ bias, float* __restrict__ C,
    int M, int Nc, int K, int lda, int aoff, int ldc, int coff)
{
    __shared__ float As[16][65];
    __shared__ float Bs[16][65];
    const int tid = threadIdx.x;
    const int bm = blockIdx.y * 64;
    const int bn = blockIdx.x * 64;
    const int tx = tid & 15;
    const int ty = tid >> 4;
    float acc[4][4] = {};

    for (int k0 = 0; k0 < K; k0 += 16) {
        {
            int r = tid >> 2, cs = (tid & 3) * 4;
            float4 v = *reinterpret_cast<const float4*>(
                A + (size_t)(bm + r) * lda + aoff + k0 + cs);
            As[cs + 0][r] = v.x; As[cs + 1][r] = v.y;
            As[cs + 2][r] = v.z; As[cs + 3][r] = v.w;
        }
        if (TRANSB) {
            int n = tid >> 2, ks = (tid & 3) * 4;
            float4 v = *reinterpret_cast<const float4*>(
                Bm + (size_t)(bn + n) * K + k0 + ks);
            Bs[ks + 0][n] = v.x; Bs[ks + 1][n] = v.y;
            Bs[ks + 2][n] = v.z; Bs[ks + 3][n] = v.w;
        } else {
            int r = tid >> 4, cs = (tid & 15) * 4;
            float4 v = *reinterpret_cast<const float4*>(
                Bm + (size_t)(k0 + r) * Nc + bn + cs);
            Bs[r][cs + 0] = v.x; Bs[r][cs + 1] = v.y;
            Bs[r][cs + 2] = v.z; Bs[r][cs + 3] = v.w;
        }
        __syncthreads();
#pragma unroll
        for (int k = 0; k < 16; ++k) {
            float a[4], bv[4];
#pragma unroll
            for (int q = 0; q < 4; ++q) a[q] = As[k][ty * 4 + q];
#pragma unroll
            for (int q = 0; q < 4; ++q) bv[q] = Bs[k][tx * 4 + q];
#pragma unroll
            for (int p = 0; p < 4; ++p)
#pragma unroll
                for (int q = 0; q < 4; ++q)
                    acc[p][q] = fmaf(a[p], bv[q], acc[p][q]);
        }
        __syncthreads();
    }
#pragma unroll
    for (int p = 0; p < 4; ++p) {
        const int m = bm + ty * 4 + p;
#pragma unroll
        for (int q = 0; q < 4; ++q) {
            const int n = bn + tx * 4 + q;
            float v = acc[p][q] + bias[n];
            if (RELU) v = fmaxf(v, 0.f);
            C[(size_t)m * ldc + coff + n] = v;
        }
    }
}

__global__ void transpose_kernel(const float* __restrict__ src,
                                 float* __restrict__ dst, int R, int Cc)
{
    __shared__ float tile[32][33];
    int c = blockIdx.x * 32 + threadIdx.x;
    int r = blockIdx.y * 32 + threadIdx.y;
    if (r < R && c < Cc) tile[threadIdx.y][threadIdx.x] = src[(size_t)r * Cc + c];
    __syncthreads();
    int dr = blockIdx.x * 32 + threadIdx.y;
    int dc = blockIdx.y * 32 + threadIdx.x;
    if (dr < Cc && dc < R) dst[(size_t)dr * R + dc] = tile[threadIdx.x][threadIdx.y];
}

__global__ __launch_bounds__(576, 1) void scan_kernel(
    const float* __restrict__ adj, const float* __restrict__ smask,
    const float* __restrict__ GIc, const float* __restrict__ GHp,
    const float* __restrict__ cwhhT, const float* __restrict__ pwihT,
    const float* __restrict__ cbhh, const float* __restrict__ pbih,
    const float* __restrict__ wr0T, const float* __restrict__ wr1T,
    const float* __restrict__ wk,
    float* __restrict__ Hcat, int layer,
    float* __restrict__ V0, float* __restrict__ V1,
    float* __restrict__ attn_out)
{
    __shared__ float s_Ksc[Nn];
    __shared__ float s_a0[Nn], s_a1[Nn];
    __shared__ float s_red[18], s_red2[18];
    __shared__ float s_Mpart[G3];
    __shared__ float s_M[DH];
    __shared__ float s_ghC[G3], s_giP[G3];
    __shared__ float s_H[DH];
    __shared__ float s_cb[G3], s_pb[G3], s_wk[DH];

    const int t = threadIdx.x;
    const int b = blockIdx.x;
    const int lane = t & 31;
    const int warp = t >> 5;

    s_cb[t] = cbhh[t];
    s_pb[t] = pbih[t];
    if (t < DH) s_wk[t] = wk[t];
    if (t < Nn) s_Ksc[t] = 0.f;
    __syncthreads();

    const int dcol = t % DH;
    const int chunk = t / DH;

    for (int i = 0; i < Nn; ++i) {
        const size_t row = (size_t)b * Nn + i;

        // Phase A: masked softmax over Ksc (x@wq + gat_b cancel)
        float sc = -3.0e38f, smv = 0.f;
        bool valid = false;
        if (t < Nn) {
            valid = (t < i) && (adj[row * Nn + t] > 0.5f);
            smv = smask[row * Nn + t];
            if (valid) sc = s_Ksc[t];
        }
        float wm = warpRedMax(sc);
        if (lane == 0) s_red[warp] = wm;
        __syncthreads();
        float mx = s_red[0];
#pragma unroll
        for (int q = 1; q < 8; ++q) mx = fmaxf(mx, s_red[q]);
        float e = valid ? expf(sc - mx) : 0.f;
        float ws = warpRedSum(e);
        if (lane == 0) s_red2[warp] = ws;
        __syncthreads();
        float tot = s_red2[0];
#pragma unroll
        for (int q = 1; q < 8; ++q) tot += s_red2[q];
        if (t < Nn) {
            float attn = 0.f;
            if (i > 0) attn = e / tot;
            float a0 = attn * smv;
            s_a0[t] = a0;
            s_a1[t] = attn - a0;
            attn_out[(((size_t)b * Ll + layer) * Nn + i) * Nn + t] = attn;
        }
        __syncthreads();

        // Phase B: M = sum_{n<i} a0[n]*V0[n,:] + a1[n]*V1[n,:]
        {
            float acc = 0.f;
            const float* v0p = V0 + ((size_t)b * Nn) * DH + dcol;
            const float* v1p = V1 + ((size_t)b * Nn) * DH + dcol;
            for (int n = chunk; n < i; n += 3) {
                acc = fmaf(s_a0[n], __ldg(v0p + (size_t)n * DH), acc);
                acc = fmaf(s_a1[n], __ldg(v1p + (size_t)n * DH), acc);
            }
            s_Mpart[t] = acc;
        }
        __syncthreads();
        if (t < DH) s_M[t] = s_Mpart[t] + s_Mpart[DH + t] + s_Mpart[2 * DH + t];
        __syncthreads();

        // Phase C: gh_C = M@cwhh.T + cbhh ; gi_P = M@pwih.T + pbih
        {
            float aC = s_cb[t], aP = s_pb[t];
            const float* wc = cwhhT + t;
            const float* wp = pwihT + t;
#pragma unroll 8
            for (int d = 0; d < DH; ++d) {
                float m = s_M[d];
                aC = fmaf(m, __ldg(wc + d * G3), aC);
                aP = fmaf(m, __ldg(wp + d * G3), aP);
            }
            s_ghC[t] = aC;
            s_giP[t] = aP;
        }
        __syncthreads();

        // Phase D: two GRUs, Hnew = C + P
        if (t < DH) {
            const float* gic = GIc + row * G3;
            const float* ghp = GHp + row * G3;
            float x = Hcat[row * HCW + layer * DH + t];
            float m = s_M[t];
            float rC = 1.f / (1.f + expf(-(gic[t] + s_ghC[t])));
            float zC = 1.f / (1.f + expf(-(gic[DH + t] + s_ghC[DH + t])));
            float nC = tanhf(gic[2 * DH + t] + rC * s_ghC[2 * DH + t]);
            float Cv = (1.f - zC) * nC + zC * m;
            float rP = 1.f / (1.f + expf(-(s_giP[t] + ghp[t])));
            float zP = 1.f / (1.f + expf(-(s_giP[DH + t] + ghp[DH + t])));
            float nP = tanhf(s_giP[2 * DH + t] + rP * ghp[2 * DH + t]);
            float Pv = (1.f - zP) * nP + zP * x;
            float h = Cv + Pv;
            s_H[t] = h;
            Hcat[row * HCW + (layer + 1) * DH + t] = h;
        }
        __syncthreads();

        // Phase E: V0[i,:], V1[i,:], Ksc[i]
        if (t < 2 * DH) {
            const int j = (t < DH) ? t : t - DH;
            const float* w = (t < DH) ? wr0T : wr1T;
            float a = 0.f;
#pragma unroll 8
            for (int d = 0; d < DH; ++d) a = fmaf(s_H[d], __ldg(w + d * DH + j), a);
            float* dst = (t < DH) ? V0 : V1;
            dst[row * DH + j] = a;
        } else if (t < 2 * DH + 32) {
            float s2 = 0.f;
            for (int q = lane; q < DH; q += 32) s2 += s_H[q] * s_wk[q];
            s2 = warpRedSum(s2);
            if (lane == 0) s_Ksc[i] = s2;
        }
        __syncthreads();
    }
}

extern "C" void kernel_launch(void* const* d_in, const int* in_sizes, int n_in,
                              void* d_out, int out_size)
{
    (void)in_sizes; (void)n_in; (void)out_size;
    const float* features = (const float*)d_in[0];
    const float* adj      = (const float*)d_in[1];
    const float* smask    = (const float*)d_in[2];
    const float* fc1_w    = (const float*)d_in[5];
    const float* fc1_b    = (const float*)d_in[6];
    const float* gat_w    = (const float*)d_in[7];
    const float* wr0      = (const float*)d_in[9];
    const float* wr1      = (const float*)d_in[10];
    const float* gruc_wih = (const float*)d_in[11];
    const float* gruc_whh = (const float*)d_in[12];
    const float* gruc_bih = (const float*)d_in[13];
    const float* gruc_bhh = (const float*)d_in[14];
    const float* grup_wih = (const float*)d_in[15];
    const float* grup_whh = (const float*)d_in[16];
    const float* grup_bih = (const float*)d_in[17];
    const float* grup_bhh = (const float*)d_in[18];
    const float* mlp_w0   = (const float*)d_in[19];
    const float* mlp_b0   = (const float*)d_in[20];
    const float* mlp_w1   = (const float*)d_in[21];
    const float* mlp_b1   = (const float*)d_in[22];
    const float* mlp_w2   = (const float*)d_in[23];
    const float* mlp_b2   = (const float*)d_in[24];

    float *pHcat, *pGI, *pGH, *pV0, *pV1, *ph1, *ph2, *pWT;
    cudaGetSymbolAddress((void**)&pHcat, g_Hcat);
    cudaGetSymbolAddress((void**)&pGI, g_GI);
    cudaGetSymbolAddress((void**)&pGH, g_GH);
    cudaGetSymbolAddress((void**)&pV0, g_V0);
    cudaGetSymbolAddress((void**)&pV1, g_V1);
    cudaGetSymbolAddress((void**)&ph1, g_h1);
    cudaGetSymbolAddress((void**)&ph2, g_h2);
    cudaGetSymbolAddress((void**)&pWT, g_WT);

    float* out = (float*)d_out;
    float* out_attn = out + (size_t)Bb * Nn * DCc;

    const int M = Bb * Nn;
    const dim3 blk(256);

    gemm_kernel<0, 1><<<dim3(DH / 64, M / 64), blk>>>(
        features, fc1_w, fc1_b, pHcat, M, DH, DEe, DEe, 0, HCW, 0);

    for (int l = 0; l < Ll; ++l) {
        gemm_kernel<1, 0><<<dim3(G3 / 64, M / 64), blk>>>(
            pHcat, gruc_wih + (size_t)l * G3 * DH, gruc_bih + l * G3, pGI,
            M, G3, DH, HCW, l * DH, G3, 0);
        gemm_kernel<1, 0><<<dim3(G3 / 64, M / 64), blk>>>(
            pHcat, grup_whh + (size_t)l * G3 * DH, grup_bhh + l * G3, pGH,
            M, G3, DH, HCW, l * DH, G3, 0);
        transpose_kernel<<<dim3(6, 18), dim3(32, 32)>>>(
            gruc_whh + (size_t)l * G3 * DH, pWT, G3, DH);
        transpose_kernel<<<dim3(6, 18), dim3(32, 32)>>>(
            grup_wih + (size_t)l * G3 * DH, pWT + DH * G3, G3, DH);
        transpose_kernel<<<dim3(6, 6), dim3(32, 32)>>>(
            wr0 + (size_t)l * DH * DH, pWT + 2 * DH * G3, DH, DH);
        transpose_kernel<<<dim3(6, 6), dim3(32, 32)>>>(
            wr1 + (size_t)l * DH * DH, pWT + 2 * DH * G3 + DH * DH, DH, DH);

        scan_kernel<<<Bb, 576>>>(
            adj, smask, pGI, pGH,
            pWT, pWT + DH * G3,
            gruc_bhh + l * G3, grup_bih + l * G3,
            pWT + 2 * DH * G3, pWT + 2 * DH * G3 + DH * DH,
            gat_w + (size_t)l * 2 * DH + DH,
            pHcat, l, pV0, pV1, out_attn);
    }

    gemm_kernel<0, 1><<<dim3(DH / 64, M / 64), blk>>>(
        pHcat, mlp_w0, mlp_b0, ph1, M, DH, HCW, HCW, 0, DH, 0);
    gemm_kernel<0, 1><<<dim3(DH / 64, M / 64), blk>>>(
        ph1, mlp_w1, mlp_b1, ph2, M, DH, DH, DH, 0, DH, 0);
    gemm_kernel<0, 0><<<dim3(DCc / 64, M / 64), blk>>>(
        ph2, mlp_w2, mlp_b2, out, M, DCc, DH, DH, 0, DCc, 0);
}

// round 6
// speedup vs baseline: 3.4071x; 3.4071x over previous
#include <cuda_runtime.h>
#include <cuda_bf16.h>
#include <cstdint>
#include <math.h>

#define Bb 8
#define Nn 256
#define DEe 768
#define DH 192
#define Ll 2
#define DCc 192
#define G3 576
#define HCW 576
#define CSZ 8           // cluster size (CTAs per batch)
#define DSL 24          // DH / CSZ columns per CTA

// ---- smem float offsets (scan kernel) ----
#define OFF_WC   0                    // 48*72*4 = 13824
#define OFF_WP   13824                // 13824
#define OFF_WR0  27648                // 48*24*4 = 4608
#define OFF_WR1  32256                // 4608
#define OFF_V0   36864                // 256*24 = 6144
#define OFF_V1   43008                // 6144
#define OFF_KSC  49152                // 256
#define OFF_A0   49408                // 256
#define OFF_A1   49664                // 256
#define OFF_M    49920                // 192 (16B aligned)
#define OFF_H    50112                // 192 (16B aligned)
#define OFF_WK   50304                // 192
#define OFF_GC   50496                // 72
#define OFF_GP   50568                // 72
#define OFF_GI   50640                // 72
#define OFF_GH   50712                // 72
#define OFF_X    50784                // 24
#define OFF_MP   50808                // 8*24 = 192
#define OFF_BC   51000                // 72
#define OFF_BP   51072                // 72
#define OFF_RED  51144                // 8
#define OFF_RED2 51152                // 8
#define SCAN_SMEM_FLOATS 51160
#define SCAN_SMEM_BYTES (SCAN_SMEM_FLOATS * 4)

__device__ float g_Hcat[Bb * Nn * HCW];
__device__ float g_GI[Bb * Nn * G3];
__device__ float g_GH[Bb * Nn * G3];
__device__ float g_h1[Bb * Nn * DH];
__device__ float g_h2[Bb * Nn * DH];

__device__ __forceinline__ float warpRedMax(float v) {
#pragma unroll
    for (int o = 16; o > 0; o >>= 1) v = fmaxf(v, __shfl_xor_sync(0xffffffffu, v, o));
    return v;
}
__device__ __forceinline__ float warpRedSum(float v) {
#pragma unroll
    for (int o = 16; o > 0; o >>= 1) v += __shfl_xor_sync(0xffffffffu, v, o);
    return v;
}
__device__ __forceinline__ void cluster_sync_() {
    asm volatile("barrier.cluster.arrive.aligned;" ::: "memory");
    asm volatile("barrier.cluster.wait.aligned;" ::: "memory");
}
__device__ __forceinline__ uint32_t smem_u32(const void* p) {
    uint32_t a;
    asm("{ .reg .u64 t; cvta.to.shared.u64 t, %1; cvt.u32.u64 %0, t; }" : "=r"(a) : "l"(p));
    return a;
}
// store v to the same smem slot in all 8 cluster CTAs
__device__ __forceinline__ void st_all_ranks(float* p, float v) {
    uint32_t a = smem_u32(p);
#pragma unroll
    for (int r = 0; r < CSZ; ++r) {
        uint32_t ra;
        asm volatile("mapa.shared::cluster.u32 %0, %1, %2;" : "=r"(ra) : "r"(a), "r"(r));
        asm volatile("st.shared::cluster.f32 [%0], %1;" :: "r"(ra), "f"(v) : "memory");
    }
}

// ---------------- generic tiled SGEMM (prologue / epilogue) ----------------
template <int TRANSB, int RELU>
__global__ __launch_bounds__(256) void gemm_kernel(
    const float* __restrict__ A, const float* __restrict__ Bm,
    const float* __restrict__ bias, float* __restrict__ C,
    int M, int Nc, int K, int lda, int aoff, int ldc, int coff)
{
    __shared__ float As[16][65];
    __shared__ float Bs[16][65];
    const int tid = threadIdx.x;
    const int bm = blockIdx.y * 64;
    const int bn = blockIdx.x * 64;
    const int tx = tid & 15;
    const int ty = tid >> 4;
    float acc[4][4] = {};

    for (int k0 = 0; k0 < K; k0 += 16) {
        {
            int r = tid >> 2, cs = (tid & 3) * 4;
            float4 v = *reinterpret_cast<const float4*>(
                A + (size_t)(bm + r) * lda + aoff + k0 + cs);
            As[cs + 0][r] = v.x; As[cs + 1][r] = v.y;
            As[cs + 2][r] = v.z; As[cs + 3][r] = v.w;
        }
        if (TRANSB) {
            int n = tid >> 2, ks = (tid & 3) * 4;
            float4 v = *reinterpret_cast<const float4*>(
                Bm + (size_t)(bn + n) * K + k0 + ks);
            Bs[ks + 0][n] = v.x; Bs[ks + 1][n] = v.y;
            Bs[ks + 2][n] = v.z; Bs[ks + 3][n] = v.w;
        } else {
            int r = tid >> 4, cs = (tid & 15) * 4;
            float4 v = *reinterpret_cast<const float4*>(
                Bm + (size_t)(k0 + r) * Nc + bn + cs);
            Bs[r][cs + 0] = v.x; Bs[r][cs + 1] = v.y;
            Bs[r][cs + 2] = v.z; Bs[r][cs + 3] = v.w;
        }
        __syncthreads();
#pragma unroll
        for (int k = 0; k < 16; ++k) {
            float a[4], bv[4];
#pragma unroll
            for (int q = 0; q < 4; ++q) a[q] = As[k][ty * 4 + q];
#pragma unroll
            for (int q = 0; q < 4; ++q) bv[q] = Bs[k][tx * 4 + q];
#pragma unroll
            for (int p = 0; p < 4; ++p)
#pragma unroll
                for (int q = 0; q < 4; ++q)
                    acc[p][q] = fmaf(a[p], bv[q], acc[p][q]);
        }
        __syncthreads();
    }
#pragma unroll
    for (int p = 0; p < 4; ++p) {
        const int m = bm + ty * 4 + p;
#pragma unroll
        for (int q = 0; q < 4; ++q) {
            const int n = bn + tx * 4 + q;
            float v = acc[p][q] + bias[n];
            if (RELU) v = fmaxf(v, 0.f);
            C[(size_t)m * ldc + coff + n] = v;
        }
    }
}

// ---------------- clustered scan: 8 CTAs per batch, smem-resident state ----
__global__ __launch_bounds__(256, 1) void scan2_kernel(
    const float* __restrict__ adj, const float* __restrict__ smask,
    const float* __restrict__ GIc, const float* __restrict__ GHp,
    const float* __restrict__ cwhh,   // (576,192) raw
    const float* __restrict__ pwih,   // (576,192) raw
    const float* __restrict__ cbhh, const float* __restrict__ pbih,
    const float* __restrict__ wr0, const float* __restrict__ wr1, // (192,192) raw
    const float* __restrict__ wk,
    float* __restrict__ Hcat, int layer,
    float* __restrict__ attn_out)
{
    extern __shared__ float sm[];
    const int t = threadIdx.x;
    const int lane = t & 31;
    const int warp = t >> 5;
    uint32_t c;
    asm("mov.u32 %0, %%cluster_ctarank;" : "=r"(c));
    const int b = blockIdx.x / CSZ;

    // ---- prologue: load weight slices into smem ----
    for (int idx = t; idx < 72 * 48; idx += 256) {
        int o = idx / 48, d4 = idx % 48;
        int col = (o / DSL) * DH + c * DSL + (o % DSL);
        float4 vc = *reinterpret_cast<const float4*>(cwhh + (size_t)col * DH + 4 * d4);
        float4 vp = *reinterpret_cast<const float4*>(pwih + (size_t)col * DH + 4 * d4);
        float* dc = sm + OFF_WC + (d4 * 72 + o) * 4;
        float* dp = sm + OFF_WP + (d4 * 72 + o) * 4;
        dc[0] = vc.x; dc[1] = vc.y; dc[2] = vc.z; dc[3] = vc.w;
        dp[0] = vp.x; dp[1] = vp.y; dp[2] = vp.z; dp[3] = vp.w;
    }
    for (int idx = t; idx < DSL * 48; idx += 256) {
        int j = idx / 48, d4 = idx % 48;
        int r0 = c * DSL + j;
        float4 v0 = *reinterpret_cast<const float4*>(wr0 + (size_t)r0 * DH + 4 * d4);
        float4 v1 = *reinterpret_cast<const float4*>(wr1 + (size_t)r0 * DH + 4 * d4);
        float* d0 = sm + OFF_WR0 + (d4 * DSL + j) * 4;
        float* d1 = sm + OFF_WR1 + (d4 * DSL + j) * 4;
        d0[0] = v0.x; d0[1] = v0.y; d0[2] = v0.z; d0[3] = v0.w;
        d1[0] = v1.x; d1[1] = v1.y; d1[2] = v1.z; d1[3] = v1.w;
    }
    if (t < 72) {
        int col = (t / DSL) * DH + c * DSL + (t % DSL);
        sm[OFF_BC + t] = cbhh[col];
        sm[OFF_BP + t] = pbih[col];
    }
    if (t < DH) sm[OFF_WK + t] = wk[t];
    if (t < Nn) sm[OFF_KSC + t] = 0.f;
    __syncthreads();
    cluster_sync_();

    const int dB = t % DSL;
    const int gB = t / DSL;
    const float4* sM4 = reinterpret_cast<const float4*>(sm + OFF_M);
    const float4* sH4 = reinterpret_cast<const float4*>(sm + OFF_H);

    for (int i = 0; i < Nn; ++i) {
        const size_t row = (size_t)b * Nn + i;

        // ---- Phase A: masked softmax over Ksc (x@wq + gat_b cancel) ----
        float sc = -3.0e38f, smv = 0.f;
        bool valid = false;
        {
            valid = (t < i) && (adj[row * Nn + t] > 0.5f);
            smv = smask[row * Nn + t];
            if (valid) sc = sm[OFF_KSC + t];
        }
        float wm = warpRedMax(sc);
        if (lane == 0) sm[OFF_RED + warp] = wm;
        __syncthreads();
        float mx = sm[OFF_RED + 0];
#pragma unroll
        for (int q = 1; q < 8; ++q) mx = fmaxf(mx, sm[OFF_RED + q]);
        float e = valid ? expf(sc - mx) : 0.f;
        float ws = warpRedSum(e);
        if (lane == 0) sm[OFF_RED2 + warp] = ws;
        __syncthreads();
        float tot = sm[OFF_RED2 + 0];
#pragma unroll
        for (int q = 1; q < 8; ++q) tot += sm[OFF_RED2 + q];
        {
            float attn = 0.f;
            if (i > 0) attn = e / tot;
            float a0 = attn * smv;
            sm[OFF_A0 + t] = a0;
            sm[OFF_A1 + t] = attn - a0;
            if (c == 0)
                attn_out[(((size_t)b * Ll + layer) * Nn + i) * Nn + t] = attn;
        }
        __syncthreads();

        // ---- Phase B: partial M over owned columns; threads>=192 prefetch ----
        if (t < 192) {
            float acc = 0.f;
            for (int n = gB; n < i; n += 8) {
                acc = fmaf(sm[OFF_A0 + n], sm[OFF_V0 + n * DSL + dB], acc);
                acc = fmaf(sm[OFF_A1 + n], sm[OFF_V1 + n * DSL + dB], acc);
            }
            sm[OFF_MP + gB * DSL + dB] = acc;
        } else {
            int tp = t - 192;
            for (int u = tp; u < 168; u += 64) {
                if (u < 72) {
                    int col = (u / DSL) * DH + c * DSL + (u % DSL);
                    sm[OFF_GI + u] = GIc[row * G3 + col];
                } else if (u < 144) {
                    int uu = u - 72;
                    int col = (uu / DSL) * DH + c * DSL + (uu % DSL);
                    sm[OFF_GH + uu] = GHp[row * G3 + col];
                } else {
                    int j = u - 144;
                    sm[OFF_X + j] = Hcat[row * HCW + layer * DH + c * DSL + j];
                }
            }
        }
        __syncthreads();
        if (t < DSL) {
            float v = 0.f;
#pragma unroll
            for (int g = 0; g < 8; ++g) v += sm[OFF_MP + g * DSL + t];
            st_all_ranks(sm + OFF_M + c * DSL + t, v);
        }
        cluster_sync_();   // #1 : full M everywhere

        // ---- Phase C: gh_C / gi_P for owned 72+72 outputs ----
        if (t < 144) {
            const int isP = (t >= 72);
            const int o = isP ? t - 72 : t;
            const float* W = sm + (isP ? OFF_WP : OFF_WC);
            float a0 = isP ? sm[OFF_BP + o] : sm[OFF_BC + o];
            float a1 = 0.f, a2 = 0.f, a3 = 0.f;
#pragma unroll 8
            for (int d4 = 0; d4 < 48; ++d4) {
                float4 m4 = sM4[d4];
                const float4 w4 = *reinterpret_cast<const float4*>(W + (d4 * 72 + o) * 4);
                a0 = fmaf(m4.x, w4.x, a0);
                a1 = fmaf(m4.y, w4.y, a1);
                a2 = fmaf(m4.z, w4.z, a2);
                a3 = fmaf(m4.w, w4.w, a3);
            }
            sm[(isP ? OFF_GP : OFF_GC) + o] = (a0 + a1) + (a2 + a3);
        }
        __syncthreads();

        // ---- Phase D: GRUs for owned 24 columns, broadcast H ----
        if (t < DSL) {
            const int j = t;
            float rC = 1.f / (1.f + expf(-(sm[OFF_GI + j] + sm[OFF_GC + j])));
            float zC = 1.f / (1.f + expf(-(sm[OFF_GI + 24 + j] + sm[OFF_GC + 24 + j])));
            float nC = tanhf(sm[OFF_GI + 48 + j] + rC * sm[OFF_GC + 48 + j]);
            float m = sm[OFF_M + c * DSL + j];
            float Cv = (1.f - zC) * nC + zC * m;
            float rP = 1.f / (1.f + expf(-(sm[OFF_GP + j] + sm[OFF_GH + j])));
            float zP = 1.f / (1.f + expf(-(sm[OFF_GP + 24 + j] + sm[OFF_GH + 24 + j])));
            float nP = tanhf(sm[OFF_GP + 48 + j] + rP * sm[OFF_GH + 48 + j]);
            float x = sm[OFF_X + j];
            float Pv = (1.f - zP) * nP + zP * x;
            float h = Cv + Pv;
            st_all_ranks(sm + OFF_H + c * DSL + j, h);
            Hcat[row * HCW + (layer + 1) * DH + c * DSL + j] = h;
        }
        cluster_sync_();   // #2 : full H everywhere

        // ---- Phase E: V0/V1 rows (owned cols) + Ksc[i] (replicated) ----
        if (t < 2 * DSL) {
            const int which = t / DSL;
            const int j = t % DSL;
            const float* W = sm + (which ? OFF_WR1 : OFF_WR0);
            float a0 = 0.f, a1 = 0.f, a2 = 0.f, a3 = 0.f;
#pragma unroll 8
            for (int d4 = 0; d4 < 48; ++d4) {
                float4 h4 = sH4[d4];
                const float4 w4 = *reinterpret_cast<const float4*>(W + (d4 * DSL + j) * 4);
                a0 = fmaf(h4.x, w4.x, a0);
                a1 = fmaf(h4.y, w4.y, a1);
                a2 = fmaf(h4.z, w4.z, a2);
                a3 = fmaf(h4.w, w4.w, a3);
            }
            sm[(which ? OFF_V1 : OFF_V0) + i * DSL + j] = (a0 + a1) + (a2 + a3);
        } else if (t >= 64 && t < 96) {
            float s2 = 0.f;
            for (int q = lane; q < DH; q += 32) s2 += sm[OFF_H + q] * sm[OFF_WK + q];
            s2 = warpRedSum(s2);
            if (lane == 0) sm[OFF_KSC + i] = s2;
        }
        __syncthreads();
    }
}

extern "C" void kernel_launch(void* const* d_in, const int* in_sizes, int n_in,
                              void* d_out, int out_size)
{
    (void)in_sizes; (void)n_in; (void)out_size;
    const float* features = (const float*)d_in[0];
    const float* adj      = (const float*)d_in[1];
    const float* smask    = (const float*)d_in[2];
    const float* fc1_w    = (const float*)d_in[5];
    const float* fc1_b    = (const float*)d_in[6];
    const float* gat_w    = (const float*)d_in[7];
    const float* wr0      = (const float*)d_in[9];
    const float* wr1      = (const float*)d_in[10];
    const float* gruc_wih = (const float*)d_in[11];
    const float* gruc_whh = (const float*)d_in[12];
    const float* gruc_bih = (const float*)d_in[13];
    const float* gruc_bhh = (const float*)d_in[14];
    const float* grup_wih = (const float*)d_in[15];
    const float* grup_whh = (const float*)d_in[16];
    const float* grup_bih = (const float*)d_in[17];
    const float* grup_bhh = (const float*)d_in[18];
    const float* mlp_w0   = (const float*)d_in[19];
    const float* mlp_b0   = (const float*)d_in[20];
    const float* mlp_w1   = (const float*)d_in[21];
    const float* mlp_b1   = (const float*)d_in[22];
    const float* mlp_w2   = (const float*)d_in[23];
    const float* mlp_b2   = (const float*)d_in[24];

    float *pHcat, *pGI, *pGH, *ph1, *ph2;
    cudaGetSymbolAddress((void**)&pHcat, g_Hcat);
    cudaGetSymbolAddress((void**)&pGI, g_GI);
    cudaGetSymbolAddress((void**)&pGH, g_GH);
    cudaGetSymbolAddress((void**)&ph1, g_h1);
    cudaGetSymbolAddress((void**)&ph2, g_h2);

    float* out = (float*)d_out;
    float* out_attn = out + (size_t)Bb * Nn * DCc;

    const int M = Bb * Nn;
    const dim3 blk(256);

    cudaFuncSetAttribute(scan2_kernel, cudaFuncAttributeMaxDynamicSharedMemorySize,
                         SCAN_SMEM_BYTES);

    gemm_kernel<0, 1><<<dim3(DH / 64, M / 64), blk>>>(
        features, fc1_w, fc1_b, pHcat, M, DH, DEe, DEe, 0, HCW, 0);

    for (int l = 0; l < Ll; ++l) {
        gemm_kernel<1, 0><<<dim3(G3 / 64, M / 64), blk>>>(
            pHcat, gruc_wih + (size_t)l * G3 * DH, gruc_bih + l * G3, pGI,
            M, G3, DH, HCW, l * DH, G3, 0);
        gemm_kernel<1, 0><<<dim3(G3 / 64, M / 64), blk>>>(
            pHcat, grup_whh + (size_t)l * G3 * DH, grup_bhh + l * G3, pGH,
            M, G3, DH, HCW, l * DH, G3, 0);

        cudaLaunchConfig_t cfg = {};
        cfg.gridDim = dim3(Bb * CSZ, 1, 1);
        cfg.blockDim = dim3(256, 1, 1);
        cfg.dynamicSmemBytes = SCAN_SMEM_BYTES;
        cudaLaunchAttribute attrs[1];
        attrs[0].id = cudaLaunchAttributeClusterDimension;
        attrs[0].val.clusterDim = {CSZ, 1, 1};
        cfg.attrs = attrs;
        cfg.numAttrs = 1;
        cudaLaunchKernelEx(&cfg, scan2_kernel,
            adj, smask, (const float*)pGI, (const float*)pGH,
            gruc_whh + (size_t)l * G3 * DH,
            grup_wih + (size_t)l * G3 * DH,
            gruc_bhh + l * G3, grup_bih + l * G3,
            wr0 + (size_t)l * DH * DH, wr1 + (size_t)l * DH * DH,
            gat_w + (size_t)l * 2 * DH + DH,
            pHcat, l, out_attn);
    }

    gemm_kernel<0, 1><<<dim3(DH / 64, M / 64), blk>>>(
        pHcat, mlp_w0, mlp_b0, ph1, M, DH, HCW, HCW, 0, DH, 0);
    gemm_kernel<0, 1><<<dim3(DH / 64, M / 64), blk>>>(
        ph1, mlp_w1, mlp_b1, ph2, M, DH, DH, DH, 0, DH, 0);
    gemm_kernel<0, 0><<<dim3(DCc / 64, M / 64), blk>>>(
        ph2, mlp_w2, mlp_b2, out, M, DCc, DH, DH, 0, DCc, 0);
}

// round 7
// speedup vs baseline: 3.7502x; 1.1007x over previous
#include <cuda_runtime.h>
#include <cuda_bf16.h>
#include <cstdint>
#include <math.h>

#define Bb 8
#define Nn 256
#define DEe 768
#define DH 192
#define Ll 2
#define DCc 192
#define G3 576
#define HCW 576
#define CSZ 8           // cluster size (CTAs per batch)
#define DSL 24          // DH / CSZ columns per CTA

// ---- smem float offsets (scan kernel) ----
#define OFF_WC   0                    // 48*72*4 = 13824
#define OFF_WP   13824                // 13824
#define OFF_WR0  27648                // 48*24*4 = 4608
#define OFF_WR1  32256                // 4608
#define OFF_V0   36864                // 256*24 = 6144
#define OFF_V1   43008                // 6144
#define OFF_KSC  49152                // 256
#define OFF_A0   49408                // 256
#define OFF_A1   49664                // 256
#define OFF_M    49920                // 192 (16B aligned)
#define OFF_H    50112                // 192 (16B aligned)
#define OFF_WK   50304                // 192
#define OFF_GC   50496                // 72
#define OFF_GP   50568                // 72
#define OFF_GI   50640                // 72
#define OFF_GH   50712                // 72
#define OFF_X    50784                // 24
#define OFF_MP   50808                // 8*24 = 192
#define OFF_BC   51000                // 72
#define OFF_BP   51072                // 72
#define OFF_RED  51144                // 8
#define OFF_RED2 51152                // 8
#define OFF_ADJ  51160                // 256 prefetched adj row
#define OFF_SM2  51416                // 256 prefetched smask row
#define OFF_MBAR 51672                // 4 floats = 2 x u64 mbarriers (8B aligned)
#define SCAN_SMEM_FLOATS 51676
#define SCAN_SMEM_BYTES (SCAN_SMEM_FLOATS * 4)

__device__ float g_Hcat[Bb * Nn * HCW];
__device__ float g_GI[Bb * Nn * G3];
__device__ float g_GH[Bb * Nn * G3];
__device__ float g_h1[Bb * Nn * DH];
__device__ float g_h2[Bb * Nn * DH];

__device__ __forceinline__ float warpRedMax(float v) {
#pragma unroll
    for (int o = 16; o > 0; o >>= 1) v = fmaxf(v, __shfl_xor_sync(0xffffffffu, v, o));
    return v;
}
__device__ __forceinline__ float warpRedSum(float v) {
#pragma unroll
    for (int o = 16; o > 0; o >>= 1) v += __shfl_xor_sync(0xffffffffu, v, o);
    return v;
}
__device__ __forceinline__ void cluster_sync_() {
    asm volatile("barrier.cluster.arrive.aligned;" ::: "memory");
    asm volatile("barrier.cluster.wait.aligned;" ::: "memory");
}
__device__ __forceinline__ uint32_t smem_u32(const void* p) {
    uint32_t a;
    asm("{ .reg .u64 t; cvta.to.shared.u64 t, %1; cvt.u32.u64 %0, t; }" : "=r"(a) : "l"(p));
    return a;
}
// async store of v to the same smem slot in all 8 cluster CTAs,
// accounting 4 bytes on each remote mbarrier.
__device__ __forceinline__ void bcast_async(float* p, uint32_t mbar_loc, float v) {
    uint32_t a = smem_u32(p);
#pragma unroll
    for (int r = 0; r < CSZ; ++r) {
        uint32_t ra, rb;
        asm("mapa.shared::cluster.u32 %0, %1, %2;" : "=r"(ra) : "r"(a), "r"(r));
        asm("mapa.shared::cluster.u32 %0, %1, %2;" : "=r"(rb) : "r"(mbar_loc), "r"(r));
        asm volatile(
            "st.async.shared::cluster.mbarrier::complete_tx::bytes.f32 [%0], %1, [%2];"
            :: "r"(ra), "f"(v), "r"(rb) : "memory");
    }
}
__device__ __forceinline__ void mbar_wait_parity(uint32_t mbar, uint32_t parity) {
    uint32_t done;
    asm volatile(
        "{\n\t.reg .pred p;\n\t"
        "mbarrier.try_wait.parity.acquire.cta.shared::cta.b64 p, [%1], %2;\n\t"
        "selp.b32 %0, 1, 0, p;\n\t}"
        : "=r"(done) : "r"(mbar), "r"(parity) : "memory");
    while (!done) {
        asm volatile(
            "{\n\t.reg .pred p;\n\t"
            "mbarrier.try_wait.parity.acquire.cta.shared::cta.b64 p, [%1], %2, 0x989680;\n\t"
            "selp.b32 %0, 1, 0, p;\n\t}"
            : "=r"(done) : "r"(mbar), "r"(parity) : "memory");
    }
}

// ---------------- generic tiled SGEMM (prologue / epilogue) ----------------
template <int TRANSB, int RELU>
__global__ __launch_bounds__(256) void gemm_kernel(
    const float* __restrict__ A, const float* __restrict__ Bm,
    const float* __restrict__ bias, float* __restrict__ C,
    int M, int Nc, int K, int lda, int aoff, int ldc, int coff)
{
    __shared__ float As[16][65];
    __shared__ float Bs[16][65];
    const int tid = threadIdx.x;
    const int bm = blockIdx.y * 64;
    const int bn = blockIdx.x * 64;
    const int tx = tid & 15;
    const int ty = tid >> 4;
    float acc[4][4] = {};

    for (int k0 = 0; k0 < K; k0 += 16) {
        {
            int r = tid >> 2, cs = (tid & 3) * 4;
            float4 v = *reinterpret_cast<const float4*>(
                A + (size_t)(bm + r) * lda + aoff + k0 + cs);
            As[cs + 0][r] = v.x; As[cs + 1][r] = v.y;
            As[cs + 2][r] = v.z; As[cs + 3][r] = v.w;
        }
        if (TRANSB) {
            int n = tid >> 2, ks = (tid & 3) * 4;
            float4 v = *reinterpret_cast<const float4*>(
                Bm + (size_t)(bn + n) * K + k0 + ks);
            Bs[ks + 0][n] = v.x; Bs[ks + 1][n] = v.y;
            Bs[ks + 2][n] = v.z; Bs[ks + 3][n] = v.w;
        } else {
            int r = tid >> 4, cs = (tid & 15) * 4;
            float4 v = *reinterpret_cast<const float4*>(
                Bm + (size_t)(k0 + r) * Nc + bn + cs);
            Bs[r][cs + 0] = v.x; Bs[r][cs + 1] = v.y;
            Bs[r][cs + 2] = v.z; Bs[r][cs + 3] = v.w;
        }
        __syncthreads();
#pragma unroll
        for (int k = 0; k < 16; ++k) {
            float a[4], bv[4];
#pragma unroll
            for (int q = 0; q < 4; ++q) a[q] = As[k][ty * 4 + q];
#pragma unroll
            for (int q = 0; q < 4; ++q) bv[q] = Bs[k][tx * 4 + q];
#pragma unroll
            for (int p = 0; p < 4; ++p)
#pragma unroll
                for (int q = 0; q < 4; ++q)
                    acc[p][q] = fmaf(a[p], bv[q], acc[p][q]);
        }
        __syncthreads();
    }
#pragma unroll
    for (int p = 0; p < 4; ++p) {
        const int m = bm + ty * 4 + p;
#pragma unroll
        for (int q = 0; q < 4; ++q) {
            const int n = bn + tx * 4 + q;
            float v = acc[p][q] + bias[n];
            if (RELU) v = fmaxf(v, 0.f);
            C[(size_t)m * ldc + coff + n] = v;
        }
    }
}

// ---------------- clustered scan: 8 CTAs per batch, smem-resident state ----
__global__ __launch_bounds__(256, 1) void scan2_kernel(
    const float* __restrict__ adj, const float* __restrict__ smask,
    const float* __restrict__ GIc, const float* __restrict__ GHp,
    const float* __restrict__ cwhh,   // (576,192) raw
    const float* __restrict__ pwih,   // (576,192) raw
    const float* __restrict__ cbhh, const float* __restrict__ pbih,
    const float* __restrict__ wr0, const float* __restrict__ wr1, // (192,192) raw
    const float* __restrict__ wk,
    float* __restrict__ Hcat, int layer,
    float* __restrict__ attn_out)
{
    extern __shared__ float sm[];
    const int t = threadIdx.x;
    const int lane = t & 31;
    const int warp = t >> 5;
    uint32_t c;
    asm("mov.u32 %0, %%cluster_ctarank;" : "=r"(c));
    const int b = blockIdx.x / CSZ;

    const uint32_t mbM = smem_u32(sm + OFF_MBAR);
    const uint32_t mbH = mbM + 8;

    // ---- prologue: load weight slices into smem ----
    for (int idx = t; idx < 72 * 48; idx += 256) {
        int o = idx / 48, d4 = idx % 48;
        int col = (o / DSL) * DH + c * DSL + (o % DSL);
        float4 vc = *reinterpret_cast<const float4*>(cwhh + (size_t)col * DH + 4 * d4);
        float4 vp = *reinterpret_cast<const float4*>(pwih + (size_t)col * DH + 4 * d4);
        float* dc = sm + OFF_WC + (d4 * 72 + o) * 4;
        float* dp = sm + OFF_WP + (d4 * 72 + o) * 4;
        dc[0] = vc.x; dc[1] = vc.y; dc[2] = vc.z; dc[3] = vc.w;
        dp[0] = vp.x; dp[1] = vp.y; dp[2] = vp.z; dp[3] = vp.w;
    }
    for (int idx = t; idx < DSL * 48; idx += 256) {
        int j = idx / 48, d4 = idx % 48;
        int r0 = c * DSL + j;
        float4 v0 = *reinterpret_cast<const float4*>(wr0 + (size_t)r0 * DH + 4 * d4);
        float4 v1 = *reinterpret_cast<const float4*>(wr1 + (size_t)r0 * DH + 4 * d4);
        float* d0 = sm + OFF_WR0 + (d4 * DSL + j) * 4;
        float* d1 = sm + OFF_WR1 + (d4 * DSL + j) * 4;
        d0[0] = v0.x; d0[1] = v0.y; d0[2] = v0.z; d0[3] = v0.w;
        d1[0] = v1.x; d1[1] = v1.y; d1[2] = v1.z; d1[3] = v1.w;
    }
    if (t < 72) {
        int col = (t / DSL) * DH + c * DSL + (t % DSL);
        sm[OFF_BC + t] = cbhh[col];
        sm[OFF_BP + t] = pbih[col];
    }
    if (t < DH) sm[OFF_WK + t] = wk[t];
    if (t < Nn) {
        sm[OFF_KSC + t] = 0.f;
        sm[OFF_ADJ + t] = 0.f;
        sm[OFF_SM2 + t] = 0.f;
    }
    if (t == 0) {
        asm volatile("mbarrier.init.shared.b64 [%0], 1;" :: "r"(mbM) : "memory");
        asm volatile("mbarrier.init.shared.b64 [%0], 1;" :: "r"(mbH) : "memory");
    }
    __syncthreads();
    cluster_sync_();   // mbarriers + smem visible cluster-wide before any st.async

    const int dB = t % DSL;
    const int gB = t / DSL;
    const float4* sM4 = reinterpret_cast<const float4*>(sm + OFF_M);
    const float4* sH4 = reinterpret_cast<const float4*>(sm + OFF_H);

    for (int i = 0; i < Nn; ++i) {
        const size_t row = (size_t)b * Nn + i;
        const uint32_t par = (uint32_t)(i & 1);

        if (t == 0) {
            asm volatile("mbarrier.arrive.expect_tx.shared.b64 _, [%0], %1;"
                         :: "r"(mbM), "r"(768u) : "memory");
            asm volatile("mbarrier.arrive.expect_tx.shared.b64 _, [%0], %1;"
                         :: "r"(mbH), "r"(768u) : "memory");
        }

        // ---- Phase A: masked softmax over Ksc (adj/smask prefetched) ----
        float sc = -3.0e38f;
        bool valid = (t < i) && (sm[OFF_ADJ + t] > 0.5f);
        float smv = sm[OFF_SM2 + t];
        if (valid) sc = sm[OFF_KSC + t];
        float wm = warpRedMax(sc);
        if (lane == 0) sm[OFF_RED + warp] = wm;
        __syncthreads();
        float mx = sm[OFF_RED + 0];
#pragma unroll
        for (int q = 1; q < 8; ++q) mx = fmaxf(mx, sm[OFF_RED + q]);
        float e = valid ? expf(sc - mx) : 0.f;
        float ws = warpRedSum(e);
        if (lane == 0) sm[OFF_RED2 + warp] = ws;
        __syncthreads();
        float tot = sm[OFF_RED2 + 0];
#pragma unroll
        for (int q = 1; q < 8; ++q) tot += sm[OFF_RED2 + q];
        {
            float attn = 0.f;
            if (i > 0) attn = e / tot;
            float a0 = attn * smv;
            sm[OFF_A0 + t] = a0;
            sm[OFF_A1 + t] = attn - a0;
            if (c == 0)
                attn_out[(((size_t)b * Ll + layer) * Nn + i) * Nn + t] = attn;
        }
        __syncthreads();

        // ---- Phase B: partial M over owned columns; threads>=192 prefetch ----
        if (t < 192) {
            float acc = 0.f;
            for (int n = gB; n < i; n += 8) {
                acc = fmaf(sm[OFF_A0 + n], sm[OFF_V0 + n * DSL + dB], acc);
                acc = fmaf(sm[OFF_A1 + n], sm[OFF_V1 + n * DSL + dB], acc);
            }
            sm[OFF_MP + gB * DSL + dB] = acc;
        } else {
            int tp = t - 192;
            for (int u = tp; u < 168; u += 64) {
                if (u < 72) {
                    int col = (u / DSL) * DH + c * DSL + (u % DSL);
                    sm[OFF_GI + u] = GIc[row * G3 + col];
                } else if (u < 144) {
                    int uu = u - 72;
                    int col = (uu / DSL) * DH + c * DSL + (uu % DSL);
                    sm[OFF_GH + uu] = GHp[row * G3 + col];
                } else {
                    int j = u - 144;
                    sm[OFF_X + j] = Hcat[row * HCW + layer * DH + c * DSL + j];
                }
            }
        }
        __syncthreads();
        if (t < DSL) {
            float v = 0.f;
#pragma unroll
            for (int g = 0; g < 8; ++g) v += sm[OFF_MP + g * DSL + t];
            bcast_async(sm + OFF_M + c * DSL + t, mbM, v);   // M exchange
        }
        mbar_wait_parity(mbM, par);   // full M everywhere

        // ---- Phase C: gh_C / gi_P for owned 72+72 outputs; others prefetch ----
        if (t < 144) {
            const int isP = (t >= 72);
            const int o = isP ? t - 72 : t;
            const float* W = sm + (isP ? OFF_WP : OFF_WC);
            float a0 = isP ? sm[OFF_BP + o] : sm[OFF_BC + o];
            float a1 = 0.f, a2 = 0.f, a3 = 0.f;
#pragma unroll 8
            for (int d4 = 0; d4 < 48; ++d4) {
                float4 m4 = sM4[d4];
                const float4 w4 = *reinterpret_cast<const float4*>(W + (d4 * 72 + o) * 4);
                a0 = fmaf(m4.x, w4.x, a0);
                a1 = fmaf(m4.y, w4.y, a1);
                a2 = fmaf(m4.z, w4.z, a2);
                a3 = fmaf(m4.w, w4.w, a3);
            }
            sm[(isP ? OFF_GP : OFF_GC) + o] = (a0 + a1) + (a2 + a3);
        } else if (i + 1 < Nn) {
            // prefetch adj/smask row i+1 for next step's Phase A
            const float4* a4 = reinterpret_cast<const float4*>(
                adj + ((size_t)b * Nn + i + 1) * Nn);
            const float4* s4 = reinterpret_cast<const float4*>(
                smask + ((size_t)b * Nn + i + 1) * Nn);
            for (int u = t - 144; u < 128; u += 112) {
                if (u < 64) reinterpret_cast<float4*>(sm + OFF_ADJ)[u] = a4[u];
                else reinterpret_cast<float4*>(sm + OFF_SM2)[u - 64] = s4[u - 64];
            }
        }
        __syncthreads();

        // ---- Phase D: GRUs for owned 24 columns, async-broadcast H ----
        if (t < DSL) {
            const int j = t;
            float rC = 1.f / (1.f + expf(-(sm[OFF_GI + j] + sm[OFF_GC + j])));
            float zC = 1.f / (1.f + expf(-(sm[OFF_GI + 24 + j] + sm[OFF_GC + 24 + j])));
            float nC = tanhf(sm[OFF_GI + 48 + j] + rC * sm[OFF_GC + 48 + j]);
            float m = sm[OFF_M + c * DSL + j];
            float Cv = (1.f - zC) * nC + zC * m;
            float rP = 1.f / (1.f + expf(-(sm[OFF_GP + j] + sm[OFF_GH + j])));
            float zP = 1.f / (1.f + expf(-(sm[OFF_GP + 24 + j] + sm[OFF_GH + 24 + j])));
            float nP = tanhf(sm[OFF_GP + 48 + j] + rP * sm[OFF_GH + 48 + j]);
            float x = sm[OFF_X + j];
            float Pv = (1.f - zP) * nP + zP * x;
            float h = Cv + Pv;
            bcast_async(sm + OFF_H + c * DSL + j, mbH, h);   // H exchange
            Hcat[row * HCW + (layer + 1) * DH + c * DSL + j] = h;
        }
        mbar_wait_parity(mbH, par);   // full H everywhere

        // ---- Phase E: V0/V1 rows (owned cols) + Ksc[i] (replicated) ----
        if (t < 2 * DSL) {
            const int which = t / DSL;
            const int j = t % DSL;
            const float* W = sm + (which ? OFF_WR1 : OFF_WR0);
            float a0 = 0.f, a1 = 0.f, a2 = 0.f, a3 = 0.f;
#pragma unroll 8
            for (int d4 = 0; d4 < 48; ++d4) {
                float4 h4 = sH4[d4];
                const float4 w4 = *reinterpret_cast<const float4*>(W + (d4 * DSL + j) * 4);
                a0 = fmaf(h4.x, w4.x, a0);
                a1 = fmaf(h4.y, w4.y, a1);
                a2 = fmaf(h4.z, w4.z, a2);
                a3 = fmaf(h4.w, w4.w, a3);
            }
            sm[(which ? OFF_V1 : OFF_V0) + i * DSL + j] = (a0 + a1) + (a2 + a3);
        } else if (t >= 64 && t < 96) {
            float s2 = 0.f;
            for (int q = lane; q < DH; q += 32) s2 += sm[OFF_H + q] * sm[OFF_WK + q];
            s2 = warpRedSum(s2);
            if (lane == 0) sm[OFF_KSC + i] = s2;
        }
        __syncthreads();
    }
    cluster_sync_();
}

extern "C" void kernel_launch(void* const* d_in, const int* in_sizes, int n_in,
                              void* d_out, int out_size)
{
    (void)in_sizes; (void)n_in; (void)out_size;
    const float* features = (const float*)d_in[0];
    const float* adj      = (const float*)d_in[1];
    const float* smask    = (const float*)d_in[2];
    const float* fc1_w    = (const float*)d_in[5];
    const float* fc1_b    = (const float*)d_in[6];
    const float* gat_w    = (const float*)d_in[7];
    const float* wr0      = (const float*)d_in[9];
    const float* wr1      = (const float*)d_in[10];
    const float* gruc_wih = (const float*)d_in[11];
    const float* gruc_whh = (const float*)d_in[12];
    const float* gruc_bih = (const float*)d_in[13];
    const float* gruc_bhh = (const float*)d_in[14];
    const float* grup_wih = (const float*)d_in[15];
    const float* grup_whh = (const float*)d_in[16];
    const float* grup_bih = (const float*)d_in[17];
    const float* grup_bhh = (const float*)d_in[18];
    const float* mlp_w0   = (const float*)d_in[19];
    const float* mlp_b0   = (const float*)d_in[20];
    const float* mlp_w1   = (const float*)d_in[21];
    const float* mlp_b1   = (const float*)d_in[22];
    const float* mlp_w2   = (const float*)d_in[23];
    const float* mlp_b2   = (const float*)d_in[24];

    float *pHcat, *pGI, *pGH, *ph1, *ph2;
    cudaGetSymbolAddress((void**)&pHcat, g_Hcat);
    cudaGetSymbolAddress((void**)&pGI, g_GI);
    cudaGetSymbolAddress((void**)&pGH, g_GH);
    cudaGetSymbolAddress((void**)&ph1, g_h1);
    cudaGetSymbolAddress((void**)&ph2, g_h2);

    float* out = (float*)d_out;
    float* out_attn = out + (size_t)Bb * Nn * DCc;

    const int M = Bb * Nn;
    const dim3 blk(256);

    cudaFuncSetAttribute(scan2_kernel, cudaFuncAttributeMaxDynamicSharedMemorySize,
                         SCAN_SMEM_BYTES);

    gemm_kernel<0, 1><<<dim3(DH / 64, M / 64), blk>>>(
        features, fc1_w, fc1_b, pHcat, M, DH, DEe, DEe, 0, HCW, 0);

    for (int l = 0; l < Ll; ++l) {
        gemm_kernel<1, 0><<<dim3(G3 / 64, M / 64), blk>>>(
            pHcat, gruc_wih + (size_t)l * G3 * DH, gruc_bih + l * G3, pGI,
            M, G3, DH, HCW, l * DH, G3, 0);
        gemm_kernel<1, 0><<<dim3(G3 / 64, M / 64), blk>>>(
            pHcat, grup_whh + (size_t)l * G3 * DH, grup_bhh + l * G3, pGH,
            M, G3, DH, HCW, l * DH, G3, 0);

        cudaLaunchConfig_t cfg = {};
        cfg.gridDim = dim3(Bb * CSZ, 1, 1);
        cfg.blockDim = dim3(256, 1, 1);
        cfg.dynamicSmemBytes = SCAN_SMEM_BYTES;
        cudaLaunchAttribute attrs[1];
        attrs[0].id = cudaLaunchAttributeClusterDimension;
        attrs[0].val.clusterDim = {CSZ, 1, 1};
        cfg.attrs = attrs;
        cfg.numAttrs = 1;
        cudaLaunchKernelEx(&cfg, scan2_kernel,
            adj, smask, (const float*)pGI, (const float*)pGH,
            gruc_whh + (size_t)l * G3 * DH,
            grup_wih + (size_t)l * G3 * DH,
            gruc_bhh + l * G3, grup_bih + l * G3,
            wr0 + (size_t)l * DH * DH, wr1 + (size_t)l * DH * DH,
            gat_w + (size_t)l * 2 * DH + DH,
            pHcat, l, out_attn);
    }

    gemm_kernel<0, 1><<<dim3(DH / 64, M / 64), blk>>>(
        pHcat, mlp_w0, mlp_b0, ph1, M, DH, HCW, HCW, 0, DH, 0);
    gemm_kernel<0, 1><<<dim3(DH / 64, M / 64), blk>>>(
        ph1, mlp_w1, mlp_b1, ph2, M, DH, DH, DH, 0, DH, 0);
    gemm_kernel<0, 0><<<dim3(DCc / 64, M / 64), blk>>>(
        ph2, mlp_w2, mlp_b2, out, M, DCc, DH, DH, 0, DCc, 0);
}